// round 8
// baseline (speedup 1.0000x reference)
#include <cuda_runtime.h>
#include <cuda_fp16.h>
#include <cstdint>
#include <cstddef>

// ---------------- problem constants ----------------
#define M_DIM 8192
#define N_DIM 4096
#define K_DIM 4096

// ---------------- GEMM tiling ----------------
#define BM 128
#define BN 128
#define BK 64                               // halves per K chunk (128 bytes per row)
#define NCHUNK (K_DIM / BK)                 // 64
#define STAGES 3
#define STAGE_A (BM * 128)                  // 16384 bytes
#define STAGE_B (BN * 128)                  // 16384 bytes
#define STAGE_BYTES (STAGE_A + STAGE_B)     // 32768
#define THREADS 256
#define UNITS_TOT ((BM + BN) * 8)           // 2048 16B units per stage
#define UPT (UNITS_TOT / THREADS)           // 8
#define SMEM_DYN (STAGES * STAGE_BYTES + 1024)

// fp16 scratch (device globals; no allocation allowed)
__device__ __half g_Xh[(size_t)M_DIM * K_DIM];
__device__ __half g_Wh[(size_t)N_DIM * K_DIM];

// ---------------- helpers ----------------
static __device__ __forceinline__ uint32_t smem_u32(const void* p) {
    uint32_t a;
    asm("{ .reg .u64 t; cvta.to.shared.u64 t, %1; cvt.u32.u64 %0, t; }" : "=r"(a) : "l"(p));
    return a;
}
static __device__ __forceinline__ uint32_t sw128(uint32_t x) { return x ^ ((x >> 3) & 0x70); }

static __device__ __forceinline__ void cp16(uint32_t s, const void* g) {
    asm volatile("cp.async.cg.shared.global [%0], [%1], 16;" :: "r"(s), "l"(g) : "memory");
}
static __device__ __forceinline__ void cp_commit() {
    asm volatile("cp.async.commit_group;" ::: "memory");
}
static __device__ __forceinline__ void cp_wait1() {
    asm volatile("cp.async.wait_group 1;" ::: "memory");
}

#define LDSM_X4(r0, r1, r2, r3, addr)                                         \
    asm volatile("ldmatrix.sync.aligned.m8n8.x4.shared.b16 {%0,%1,%2,%3}, [%4];" \
                 : "=r"(r0), "=r"(r1), "=r"(r2), "=r"(r3) : "r"(addr))

#define MMA16816(c0, c1, c2, c3, a0, a1, a2, a3, b0, b1)                      \
    asm volatile("mma.sync.aligned.m16n8k16.row.col.f32.f16.f16.f32 "         \
                 "{%0,%1,%2,%3}, {%4,%5,%6,%7}, {%8,%9}, {%0,%1,%2,%3};"      \
                 : "+f"(c0), "+f"(c1), "+f"(c2), "+f"(c3)                     \
                 : "r"(a0), "r"(a1), "r"(a2), "r"(a3), "r"(b0), "r"(b1))

// ---------------- prep kernels ----------------
// One block (128 threads) per quantization group: absmax -> int4 fake quant -> fp16
__global__ void quant_kernel(const float* __restrict__ w) {
    const int g = blockIdx.x;          // group id; data contiguous: w[g*128 + t]
    const int t = threadIdx.x;
    float v = w[(size_t)g * 128 + t];
    float a = fabsf(v);
    #pragma unroll
    for (int o = 16; o > 0; o >>= 1) a = fmaxf(a, __shfl_xor_sync(0xFFFFFFFFu, a, o));
    __shared__ float red[4];
    if ((t & 31) == 0) red[t >> 5] = a;
    __syncthreads();
    float am = fmaxf(fmaxf(red[0], red[1]), fmaxf(red[2], red[3]));
    float scale = am / 7.0f;
    float safe = (scale > 0.0f) ? scale : 1.0f;
    float q = rintf(v / safe);                 // round-half-even, matches jnp.round
    q = fminf(fmaxf(q, -8.0f), 7.0f);
    g_Wh[(size_t)g * 128 + t] = __float2half_rn(q * scale);
}

__global__ void cvt_kernel(const float4* __restrict__ x, int n4) {
    int i = blockIdx.x * blockDim.x + threadIdx.x;
    if (i < n4) {
        float4 v = x[i];
        __half2* o = reinterpret_cast<__half2*>(g_Xh);
        o[2 * i + 0] = __floats2half2_rn(v.x, v.y);
        o[2 * i + 1] = __floats2half2_rn(v.z, v.w);
    }
}

// ---------------- GEMM kernel ----------------
// 128x128 CTA tile, BK=64 halves, 3-stage cp.async, mma.sync m16n8k16 (HMMA).
// 8 warps in 2(m) x 4(n): warp tile 64x32.
__global__ void __launch_bounds__(THREADS, 2)
gemm_kernel(const float* __restrict__ bias, float* __restrict__ out) {
    extern __shared__ char dsm[];
    const uint32_t tiles = (smem_u32(dsm) + 1023u) & ~1023u;

    const int tid = threadIdx.x;
    const int m0 = blockIdx.y * BM;
    const int n0 = blockIdx.x * BN;

    // ---- per-thread cp.async unit mapping (8 x 16B) ----
    uint32_t soff[UPT];
    const __half* gb[UPT];
    #pragma unroll
    for (int i = 0; i < UPT; ++i) {
        int u = i * THREADS + tid;
        if (u < BM * 8) {                          // A units
            int r = u >> 3, j = u & 7;
            soff[i] = sw128((uint32_t)(r * 128 + j * 16));
            gb[i] = g_Xh + (size_t)(m0 + r) * K_DIM + j * 8;
        } else {                                   // B units
            int v = u - BM * 8;
            int r = v >> 3, j = v & 7;
            soff[i] = (uint32_t)STAGE_A + sw128((uint32_t)(r * 128 + j * 16));
            gb[i] = g_Wh + (size_t)(n0 + r) * K_DIM + j * 8;
        }
    }

    // ---- warp/lane geometry ----
    const int warp = tid >> 5, lane = tid & 31;
    const int wm = warp >> 2;                       // 0..1  -> m offset wm*64
    const int wn = warp & 3;                        // 0..3  -> n offset wn*32

    // ldmatrix per-lane address components (byte offsets inside a stage)
    const int arow = wm * 64 + (lane & 15);
    const uint32_t a_base_off = (uint32_t)arow * 128;
    const uint32_t a_xor = ((uint32_t)arow & 7u) << 4;
    const uint32_t a_ku = ((uint32_t)lane >> 4) * 16;

    const int brow = wn * 32 + (lane & 15);
    const uint32_t b_base_off = (uint32_t)STAGE_A + (uint32_t)brow * 128;
    const uint32_t b_xor = ((uint32_t)brow & 7u) << 4;
    const uint32_t b_ku = ((uint32_t)lane >> 4) * 16;

    float acc[4][4][4];
    #pragma unroll
    for (int i = 0; i < 4; ++i)
        #pragma unroll
        for (int j = 0; j < 4; ++j)
            #pragma unroll
            for (int k = 0; k < 4; ++k) acc[i][j][k] = 0.0f;

    // ---- prologue: stages 0,1 ----
    #pragma unroll
    for (int p = 0; p < 2; ++p) {
        const uint32_t sb = tiles + p * STAGE_BYTES;
        const int koff = p * BK;
        #pragma unroll
        for (int i = 0; i < UPT; ++i) cp16(sb + soff[i], gb[i] + koff);
        cp_commit();
    }

    // ---- main loop ----
    for (int c = 0; c < NCHUNK; ++c) {
        cp_wait1();
        __syncthreads();

        // issue chunk c+2 into stage (c+2)%3
        if (c + 2 < NCHUNK) {
            const uint32_t sb = tiles + ((c + 2) % STAGES) * STAGE_BYTES;
            const int koff = (c + 2) * BK;
            #pragma unroll
            for (int i = 0; i < UPT; ++i) cp16(sb + soff[i], gb[i] + koff);
        }
        cp_commit();

        // compute chunk c from stage c%3
        const uint32_t st = tiles + (c % STAGES) * STAGE_BYTES;
        const uint32_t abase = st + a_base_off;
        const uint32_t bbase = st + b_base_off;

        #pragma unroll
        for (int kk = 0; kk < 4; ++kk) {
            const uint32_t acol = ((uint32_t)(kk * 32) + a_ku) ^ a_xor;
            const uint32_t bcol = ((uint32_t)(kk * 32) + b_ku) ^ b_xor;

            uint32_t a[4][4];
            #pragma unroll
            for (int mt = 0; mt < 4; ++mt)
                LDSM_X4(a[mt][0], a[mt][1], a[mt][2], a[mt][3],
                        abase + (uint32_t)(mt * 2048) + acol);

            // B: non-trans ldmatrix. SMEM tile is [n][k] with k contiguous, which
            // IS the col-major k x n layout the B fragment wants: thread t gets
            // B[k=(t%4)*2+{0,1}][n=t/4] per 8x8 matrix.
            uint32_t rb[2][4];
            #pragma unroll
            for (int ng = 0; ng < 2; ++ng)
                LDSM_X4(rb[ng][0], rb[ng][1], rb[ng][2], rb[ng][3],
                        bbase + (uint32_t)(ng * 2048) + bcol);

            #pragma unroll
            for (int mt = 0; mt < 4; ++mt) {
                #pragma unroll
                for (int ng = 0; ng < 2; ++ng) {
                    // n-tile (ng*2+0): n rows [ng*16+0..7]  -> regs {rb[ng][0], rb[ng][2]}
                    MMA16816(acc[mt][ng * 2 + 0][0], acc[mt][ng * 2 + 0][1],
                             acc[mt][ng * 2 + 0][2], acc[mt][ng * 2 + 0][3],
                             a[mt][0], a[mt][1], a[mt][2], a[mt][3],
                             rb[ng][0], rb[ng][2]);
                    // n-tile (ng*2+1): n rows [ng*16+8..15] -> regs {rb[ng][1], rb[ng][3]}
                    MMA16816(acc[mt][ng * 2 + 1][0], acc[mt][ng * 2 + 1][1],
                             acc[mt][ng * 2 + 1][2], acc[mt][ng * 2 + 1][3],
                             a[mt][0], a[mt][1], a[mt][2], a[mt][3],
                             rb[ng][1], rb[ng][3]);
                }
            }
        }
    }

    // ---- epilogue: bias + store fp32 ----
    {
        const int r0 = m0 + wm * 64 + (lane >> 2);
        const int cbase = n0 + wn * 32 + (lane & 3) * 2;
        const float2* bp = reinterpret_cast<const float2*>(bias + cbase);
        float2 bv[4];
        #pragma unroll
        for (int nt = 0; nt < 4; ++nt) bv[nt] = bp[nt * 4];   // +8 floats per n-tile

        #pragma unroll
        for (int mt = 0; mt < 4; ++mt) {
            const size_t rowa = (size_t)(r0 + mt * 16) * N_DIM;
            const size_t rowb = rowa + 8 * N_DIM;
            #pragma unroll
            for (int nt = 0; nt < 4; ++nt) {
                const int col = cbase + nt * 8;
                float2 o0, o1;
                o0.x = acc[mt][nt][0] + bv[nt].x;
                o0.y = acc[mt][nt][1] + bv[nt].y;
                o1.x = acc[mt][nt][2] + bv[nt].x;
                o1.y = acc[mt][nt][3] + bv[nt].y;
                *reinterpret_cast<float2*>(out + rowa + col) = o0;
                *reinterpret_cast<float2*>(out + rowb + col) = o1;
            }
        }
    }
}

// ---------------- launch ----------------
extern "C" void kernel_launch(void* const* d_in, const int* in_sizes, int n_in,
                              void* d_out, int out_size) {
    (void)in_sizes; (void)n_in; (void)out_size;
    const float* x = (const float*)d_in[0];
    const float* w = (const float*)d_in[1];
    const float* bias = (const float*)d_in[2];
    float* out = (float*)d_out;

    static int once = []() {
        cudaFuncSetAttribute(gemm_kernel, cudaFuncAttributeMaxDynamicSharedMemorySize, SMEM_DYN);
        return 0;
    }();
    (void)once;

    // 1) weight fake-quant -> fp16 (131072 groups of 128)
    quant_kernel<<<(N_DIM * K_DIM) / 128, 128>>>(w);
    // 2) x -> fp16
    const int n4 = (M_DIM * K_DIM) / 4;
    cvt_kernel<<<(n4 + 255) / 256, 256>>>((const float4*)x, n4);
    // 3) fp16 mma.sync GEMM + bias
    dim3 grid(N_DIM / BN, M_DIM / BM);
    gemm_kernel<<<grid, THREADS, SMEM_DYN>>>(bias, out);
}

// round 9
// speedup vs baseline: 1.0656x; 1.0656x over previous
#include <cuda_runtime.h>
#include <cuda_fp16.h>
#include <cstdint>
#include <cstddef>

// ---------------- problem constants ----------------
#define M_DIM 8192
#define N_DIM 4096
#define K_DIM 4096

// ---------------- GEMM tiling ----------------
#define BM 256
#define BN 128
#define BK 64                               // halves per K chunk (128 bytes per row)
#define NCHUNK (K_DIM / BK)                 // 64
#define STAGES 4
#define STAGE_A (BM * 128)                  // 32768 bytes
#define STAGE_B (BN * 128)                  // 16384 bytes
#define STAGE_BYTES (STAGE_A + STAGE_B)     // 49152
#define THREADS 256
#define UNITS_A (BM * 8)                    // 2048
#define UNITS_TOT ((BM + BN) * 8)           // 3072 16B units per stage
#define UPT (UNITS_TOT / THREADS)           // 12
#define SMEM_DYN (STAGES * STAGE_BYTES + 1024)

// fp16 scratch (device globals; no allocation allowed)
__device__ __half g_Xh[(size_t)M_DIM * K_DIM];
__device__ __half g_Wh[(size_t)N_DIM * K_DIM];

// ---------------- helpers ----------------
static __device__ __forceinline__ uint32_t smem_u32(const void* p) {
    uint32_t a;
    asm("{ .reg .u64 t; cvta.to.shared.u64 t, %1; cvt.u32.u64 %0, t; }" : "=r"(a) : "l"(p));
    return a;
}
static __device__ __forceinline__ uint32_t sw128(uint32_t x) { return x ^ ((x >> 3) & 0x70); }

static __device__ __forceinline__ void cp16(uint32_t s, const void* g) {
    asm volatile("cp.async.cg.shared.global [%0], [%1], 16;" :: "r"(s), "l"(g) : "memory");
}
static __device__ __forceinline__ void cp_commit() {
    asm volatile("cp.async.commit_group;" ::: "memory");
}
static __device__ __forceinline__ void cp_wait2() {
    asm volatile("cp.async.wait_group 2;" ::: "memory");
}

#define LDSM_X4(r0, r1, r2, r3, addr)                                         \
    asm volatile("ldmatrix.sync.aligned.m8n8.x4.shared.b16 {%0,%1,%2,%3}, [%4];" \
                 : "=r"(r0), "=r"(r1), "=r"(r2), "=r"(r3) : "r"(addr))

#define MMA16816(c0, c1, c2, c3, a0, a1, a2, a3, b0, b1)                      \
    asm volatile("mma.sync.aligned.m16n8k16.row.col.f32.f16.f16.f32 "         \
                 "{%0,%1,%2,%3}, {%4,%5,%6,%7}, {%8,%9}, {%0,%1,%2,%3};"      \
                 : "+f"(c0), "+f"(c1), "+f"(c2), "+f"(c3)                     \
                 : "r"(a0), "r"(a1), "r"(a2), "r"(a3), "r"(b0), "r"(b1))

// ---------------- prep kernels ----------------
// Warp-per-group fake quant: float4 loads, shfl-only absmax, no smem/sync.
// 8 groups per 256-thread block. 131072 groups total -> 16384 blocks.
__global__ void quant_kernel(const float4* __restrict__ w4) {
    const int warp = threadIdx.x >> 5, lane = threadIdx.x & 31;
    const size_t g = (size_t)blockIdx.x * 8 + warp;      // group id
    float4 v = w4[g * 32 + lane];
    float a = fmaxf(fmaxf(fabsf(v.x), fabsf(v.y)), fmaxf(fabsf(v.z), fabsf(v.w)));
    #pragma unroll
    for (int o = 16; o > 0; o >>= 1) a = fmaxf(a, __shfl_xor_sync(0xFFFFFFFFu, a, o));
    float scale = a / 7.0f;
    float safe = (scale > 0.0f) ? scale : 1.0f;
    float q0 = fminf(fmaxf(rintf(v.x / safe), -8.0f), 7.0f) * scale;
    float q1 = fminf(fmaxf(rintf(v.y / safe), -8.0f), 7.0f) * scale;
    float q2 = fminf(fmaxf(rintf(v.z / safe), -8.0f), 7.0f) * scale;
    float q3 = fminf(fmaxf(rintf(v.w / safe), -8.0f), 7.0f) * scale;
    __half2 h0 = __floats2half2_rn(q0, q1);
    __half2 h1 = __floats2half2_rn(q2, q3);
    uint2 u;
    u.x = *reinterpret_cast<uint32_t*>(&h0);
    u.y = *reinterpret_cast<uint32_t*>(&h1);
    *reinterpret_cast<uint2*>(g_Wh + g * 128 + lane * 4) = u;
}

__global__ void cvt_kernel(const float4* __restrict__ x, int n4) {
    int i = blockIdx.x * blockDim.x + threadIdx.x;
    if (i < n4) {
        float4 v = x[i];
        __half2* o = reinterpret_cast<__half2*>(g_Xh);
        o[2 * i + 0] = __floats2half2_rn(v.x, v.y);
        o[2 * i + 1] = __floats2half2_rn(v.z, v.w);
    }
}

// ---------------- GEMM kernel ----------------
// 256x128 CTA tile, BK=64, 4-stage cp.async (2 chunks in flight), mma.sync m16n8k16.
// 8 warps in 4(m) x 2(n): warp tile 64x64.
__global__ void __launch_bounds__(THREADS, 1)
gemm_kernel(const float* __restrict__ bias, float* __restrict__ out) {
    extern __shared__ char dsm[];
    const uint32_t tiles = (smem_u32(dsm) + 1023u) & ~1023u;

    const int tid = threadIdx.x;
    const int m0 = blockIdx.y * BM;
    const int n0 = blockIdx.x * BN;

    // ---- per-thread cp.async unit mapping (12 x 16B); units i<8 are A, i>=8 are B ----
    uint32_t soff[UPT];
    uint32_t goff[UPT];                    // element offset from g_Xh / g_Wh
    #pragma unroll
    for (int i = 0; i < UPT; ++i) {
        int u = i * THREADS + tid;
        if (u < UNITS_A) {                         // A units (i = 0..7)
            int r = u >> 3, j = u & 7;
            soff[i] = sw128((uint32_t)(r * 128 + j * 16));
            goff[i] = (uint32_t)((m0 + r) * K_DIM + j * 8);
        } else {                                   // B units (i = 8..11)
            int v = u - UNITS_A;
            int r = v >> 3, j = v & 7;
            soff[i] = (uint32_t)STAGE_A + sw128((uint32_t)(r * 128 + j * 16));
            goff[i] = (uint32_t)((n0 + r) * K_DIM + j * 8);
        }
    }

    // ---- warp/lane geometry: 4(m) x 2(n), warp tile 64x64 ----
    const int warp = tid >> 5, lane = tid & 31;
    const int wm = warp >> 1;                       // 0..3 -> m offset wm*64
    const int wn = warp & 1;                        // 0..1 -> n offset wn*64

    const int arow = wm * 64 + (lane & 15);
    const uint32_t a_base_off = (uint32_t)arow * 128;
    const uint32_t a_xor = ((uint32_t)arow & 7u) << 4;
    const uint32_t a_ku = ((uint32_t)lane >> 4) * 16;

    const int brow = wn * 64 + (lane & 15);
    const uint32_t b_base_off = (uint32_t)STAGE_A + (uint32_t)brow * 128;
    const uint32_t b_xor = ((uint32_t)brow & 7u) << 4;
    const uint32_t b_ku = ((uint32_t)lane >> 4) * 16;

    float acc[4][8][4];
    #pragma unroll
    for (int i = 0; i < 4; ++i)
        #pragma unroll
        for (int j = 0; j < 8; ++j)
            #pragma unroll
            for (int k = 0; k < 4; ++k) acc[i][j][k] = 0.0f;

    // ---- prologue: stages 0..2 ----
    #pragma unroll
    for (int p = 0; p < STAGES - 1; ++p) {
        const uint32_t sb = tiles + p * STAGE_BYTES;
        const int koff = p * BK;
        #pragma unroll
        for (int i = 0; i < UPT; ++i) {
            const __half* base = (i < 8) ? g_Xh : g_Wh;
            cp16(sb + soff[i], base + goff[i] + koff);
        }
        cp_commit();
    }

    // ---- main loop ----
    for (int c = 0; c < NCHUNK; ++c) {
        cp_wait2();
        __syncthreads();

        // issue chunk c+3 into stage (c+3)%4
        if (c + STAGES - 1 < NCHUNK) {
            const uint32_t sb = tiles + ((c + STAGES - 1) & (STAGES - 1)) * STAGE_BYTES;
            const int koff = (c + STAGES - 1) * BK;
            #pragma unroll
            for (int i = 0; i < UPT; ++i) {
                const __half* base = (i < 8) ? g_Xh : g_Wh;
                cp16(sb + soff[i], base + goff[i] + koff);
            }
        }
        cp_commit();

        // compute chunk c from stage c%4
        const uint32_t st = tiles + (c & (STAGES - 1)) * STAGE_BYTES;
        const uint32_t abase = st + a_base_off;
        const uint32_t bbase = st + b_base_off;

        #pragma unroll
        for (int kk = 0; kk < 4; ++kk) {
            const uint32_t acol = ((uint32_t)(kk * 32) + a_ku) ^ a_xor;
            const uint32_t bcol = ((uint32_t)(kk * 32) + b_ku) ^ b_xor;

            uint32_t a[4][4];
            #pragma unroll
            for (int mt = 0; mt < 4; ++mt)
                LDSM_X4(a[mt][0], a[mt][1], a[mt][2], a[mt][3],
                        abase + (uint32_t)(mt * 2048) + acol);

            // B: non-trans ldmatrix over [n][k] smem == col-major k x n fragment.
            uint32_t rb[4][4];
            #pragma unroll
            for (int ng = 0; ng < 4; ++ng)
                LDSM_X4(rb[ng][0], rb[ng][1], rb[ng][2], rb[ng][3],
                        bbase + (uint32_t)(ng * 2048) + bcol);

            #pragma unroll
            for (int mt = 0; mt < 4; ++mt) {
                #pragma unroll
                for (int ng = 0; ng < 4; ++ng) {
                    // n-tile (ng*2+0): n rows [ng*16+0..7]  -> {rb[ng][0], rb[ng][2]}
                    MMA16816(acc[mt][ng * 2 + 0][0], acc[mt][ng * 2 + 0][1],
                             acc[mt][ng * 2 + 0][2], acc[mt][ng * 2 + 0][3],
                             a[mt][0], a[mt][1], a[mt][2], a[mt][3],
                             rb[ng][0], rb[ng][2]);
                    // n-tile (ng*2+1): n rows [ng*16+8..15] -> {rb[ng][1], rb[ng][3]}
                    MMA16816(acc[mt][ng * 2 + 1][0], acc[mt][ng * 2 + 1][1],
                             acc[mt][ng * 2 + 1][2], acc[mt][ng * 2 + 1][3],
                             a[mt][0], a[mt][1], a[mt][2], a[mt][3],
                             rb[ng][1], rb[ng][3]);
                }
            }
        }
    }

    // ---- epilogue: bias + store fp32 ----
    {
        const int r0 = m0 + wm * 64 + (lane >> 2);
        const int cbase = n0 + wn * 64 + (lane & 3) * 2;
        const float2* bp = reinterpret_cast<const float2*>(bias + cbase);
        float2 bv[8];
        #pragma unroll
        for (int nt = 0; nt < 8; ++nt) bv[nt] = bp[nt * 4];   // +8 floats per n-tile

        #pragma unroll
        for (int mt = 0; mt < 4; ++mt) {
            const size_t rowa = (size_t)(r0 + mt * 16) * N_DIM;
            const size_t rowb = rowa + 8 * N_DIM;
            #pragma unroll
            for (int nt = 0; nt < 8; ++nt) {
                const int col = cbase + nt * 8;
                float2 o0, o1;
                o0.x = acc[mt][nt][0] + bv[nt].x;
                o0.y = acc[mt][nt][1] + bv[nt].y;
                o1.x = acc[mt][nt][2] + bv[nt].x;
                o1.y = acc[mt][nt][3] + bv[nt].y;
                *reinterpret_cast<float2*>(out + rowa + col) = o0;
                *reinterpret_cast<float2*>(out + rowb + col) = o1;
            }
        }
    }
}

// ---------------- launch ----------------
extern "C" void kernel_launch(void* const* d_in, const int* in_sizes, int n_in,
                              void* d_out, int out_size) {
    (void)in_sizes; (void)n_in; (void)out_size;
    const float* x = (const float*)d_in[0];
    const float* w = (const float*)d_in[1];
    const float* bias = (const float*)d_in[2];
    float* out = (float*)d_out;

    static int once = []() {
        cudaFuncSetAttribute(gemm_kernel, cudaFuncAttributeMaxDynamicSharedMemorySize, SMEM_DYN);
        return 0;
    }();
    (void)once;

    // 1) weight fake-quant -> fp16 (131072 groups; warp per group)
    quant_kernel<<<16384, 256>>>((const float4*)w);
    // 2) x -> fp16
    const int n4 = (M_DIM * K_DIM) / 4;
    cvt_kernel<<<(n4 + 255) / 256, 256>>>((const float4*)x, n4);
    // 3) fp16 mma.sync GEMM + bias
    dim3 grid(N_DIM / BN, M_DIM / BM);
    gemm_kernel<<<grid, THREADS, SMEM_DYN>>>(bias, out);
}

// round 11
// speedup vs baseline: 1.0676x; 1.0019x over previous
#include <cuda_runtime.h>
#include <cuda_fp16.h>
#include <cstdint>
#include <cstddef>

// ---------------- problem constants ----------------
#define M_DIM 8192
#define N_DIM 4096
#define K_DIM 4096

// ---------------- GEMM tiling ----------------
#define BM 256
#define BN 128
#define BK 64                               // halves per K chunk (128 bytes per row)
#define NCHUNK (K_DIM / BK)                 // 64
#define STAGES 4
#define STAGE_A (BM * 128)                  // 32768 bytes
#define STAGE_B (BN * 128)                  // 16384 bytes
#define STAGE_BYTES (STAGE_A + STAGE_B)     // 49152
#define THREADS 256
#define UNITS_A (BM * 8)                    // 2048
#define UNITS_TOT ((BM + BN) * 8)           // 3072 16B units per stage
#define UPT (UNITS_TOT / THREADS)           // 12
#define SMEM_DYN (STAGES * STAGE_BYTES + 1024)

// prep kernel split point
#define QUANT_BLOCKS 16384                  // 131072 groups / 8 per block
#define CVT_BLOCKS 32768                    // 8.39M float4 / 256

// fp16 scratch (device globals; no allocation allowed)
__device__ __half g_Xh[(size_t)M_DIM * K_DIM];
__device__ __half g_Wh[(size_t)N_DIM * K_DIM];

// ---------------- helpers ----------------
static __device__ __forceinline__ uint32_t smem_u32(const void* p) {
    uint32_t a;
    asm("{ .reg .u64 t; cvta.to.shared.u64 t, %1; cvt.u32.u64 %0, t; }" : "=r"(a) : "l"(p));
    return a;
}
static __device__ __forceinline__ uint32_t sw128(uint32_t x) { return x ^ ((x >> 3) & 0x70); }

static __device__ __forceinline__ void cp16(uint32_t s, const void* g) {
    asm volatile("cp.async.cg.shared.global [%0], [%1], 16;" :: "r"(s), "l"(g) : "memory");
}
static __device__ __forceinline__ void cp_commit() {
    asm volatile("cp.async.commit_group;" ::: "memory");
}
static __device__ __forceinline__ void cp_wait2() {
    asm volatile("cp.async.wait_group 2;" ::: "memory");
}

#define LDSM_X4(r0, r1, r2, r3, addr)                                         \
    asm volatile("ldmatrix.sync.aligned.m8n8.x4.shared.b16 {%0,%1,%2,%3}, [%4];" \
                 : "=r"(r0), "=r"(r1), "=r"(r2), "=r"(r3) : "r"(addr))

#define MMA16816(c0, c1, c2, c3, a0, a1, a2, a3, b0, b1)                      \
    asm volatile("mma.sync.aligned.m16n8k16.row.col.f32.f16.f16.f32 "         \
                 "{%0,%1,%2,%3}, {%4,%5,%6,%7}, {%8,%9}, {%0,%1,%2,%3};"      \
                 : "+f"(c0), "+f"(c1), "+f"(c2), "+f"(c3)                     \
                 : "r"(a0), "r"(a1), "r"(a2), "r"(a3), "r"(b0), "r"(b1))

// ---------------- fused prep kernel ----------------
// Blocks [0, QUANT_BLOCKS): warp-per-group int4 fake quant of weight -> g_Wh.
// Blocks [QUANT_BLOCKS, QUANT_BLOCKS+CVT_BLOCKS): x fp32 -> fp16 -> g_Xh.
__global__ void prep_kernel(const float4* __restrict__ w4, const float4* __restrict__ x4) {
    if (blockIdx.x < QUANT_BLOCKS) {
        const int warp = threadIdx.x >> 5, lane = threadIdx.x & 31;
        const size_t g = (size_t)blockIdx.x * 8 + warp;      // group id
        float4 v = w4[g * 32 + lane];
        float a = fmaxf(fmaxf(fabsf(v.x), fabsf(v.y)), fmaxf(fabsf(v.z), fabsf(v.w)));
        #pragma unroll
        for (int o = 16; o > 0; o >>= 1) a = fmaxf(a, __shfl_xor_sync(0xFFFFFFFFu, a, o));
        float scale = a / 7.0f;
        float safe = (scale > 0.0f) ? scale : 1.0f;
        float q0 = fminf(fmaxf(rintf(v.x / safe), -8.0f), 7.0f) * scale;
        float q1 = fminf(fmaxf(rintf(v.y / safe), -8.0f), 7.0f) * scale;
        float q2 = fminf(fmaxf(rintf(v.z / safe), -8.0f), 7.0f) * scale;
        float q3 = fminf(fmaxf(rintf(v.w / safe), -8.0f), 7.0f) * scale;
        __half2 h0 = __floats2half2_rn(q0, q1);
        __half2 h1 = __floats2half2_rn(q2, q3);
        uint2 u;
        u.x = *reinterpret_cast<uint32_t*>(&h0);
        u.y = *reinterpret_cast<uint32_t*>(&h1);
        *reinterpret_cast<uint2*>(g_Wh + g * 128 + lane * 4) = u;
    } else {
        const size_t i = (size_t)(blockIdx.x - QUANT_BLOCKS) * blockDim.x + threadIdx.x;
        float4 v = x4[i];
        __half2* o = reinterpret_cast<__half2*>(g_Xh);
        o[2 * i + 0] = __floats2half2_rn(v.x, v.y);
        o[2 * i + 1] = __floats2half2_rn(v.z, v.w);
    }
}

// ---------------- GEMM kernel ----------------
// 256x128 CTA tile, BK=64, 4-stage cp.async (2 chunks in flight), mma.sync m16n8k16.
// 8 warps in 4(m) x 2(n): warp tile 64x64. Register-double-buffered k-steps.
__global__ void __launch_bounds__(THREADS, 1)
gemm_kernel(const float* __restrict__ bias, float* __restrict__ out) {
    extern __shared__ char dsm[];
    const uint32_t tiles = (smem_u32(dsm) + 1023u) & ~1023u;

    const int tid = threadIdx.x;
    const int m0 = blockIdx.y * BM;
    const int n0 = blockIdx.x * BN;

    // ---- per-thread cp.async unit mapping (12 x 16B); units i<8 are A, i>=8 are B ----
    uint32_t soff[UPT];
    uint32_t goff[UPT];                    // element offset from g_Xh / g_Wh
    #pragma unroll
    for (int i = 0; i < UPT; ++i) {
        int u = i * THREADS + tid;
        if (u < UNITS_A) {                         // A units (i = 0..7)
            int r = u >> 3, j = u & 7;
            soff[i] = sw128((uint32_t)(r * 128 + j * 16));
            goff[i] = (uint32_t)((m0 + r) * K_DIM + j * 8);
        } else {                                   // B units (i = 8..11)
            int v = u - UNITS_A;
            int r = v >> 3, j = v & 7;
            soff[i] = (uint32_t)STAGE_A + sw128((uint32_t)(r * 128 + j * 16));
            goff[i] = (uint32_t)((n0 + r) * K_DIM + j * 8);
        }
    }

    // ---- warp/lane geometry: 4(m) x 2(n), warp tile 64x64 ----
    const int warp = tid >> 5, lane = tid & 31;
    const int wm = warp >> 1;                       // 0..3 -> m offset wm*64
    const int wn = warp & 1;                        // 0..1 -> n offset wn*64

    const int arow = wm * 64 + (lane & 15);
    const uint32_t a_base_off = (uint32_t)arow * 128;
    const uint32_t a_xor = ((uint32_t)arow & 7u) << 4;
    const uint32_t a_ku = ((uint32_t)lane >> 4) * 16;

    const int brow = wn * 64 + (lane & 15);
    const uint32_t b_base_off = (uint32_t)STAGE_A + (uint32_t)brow * 128;
    const uint32_t b_xor = ((uint32_t)brow & 7u) << 4;
    const uint32_t b_ku = ((uint32_t)lane >> 4) * 16;

    float acc[4][8][4];
    #pragma unroll
    for (int i = 0; i < 4; ++i)
        #pragma unroll
        for (int j = 0; j < 8; ++j)
            #pragma unroll
            for (int k = 0; k < 4; ++k) acc[i][j][k] = 0.0f;

    // ---- prologue: stages 0..2 ----
    #pragma unroll
    for (int p = 0; p < STAGES - 1; ++p) {
        const uint32_t sb = tiles + p * STAGE_BYTES;
        const int koff = p * BK;
        #pragma unroll
        for (int i = 0; i < UPT; ++i) {
            const __half* base = (i < 8) ? g_Xh : g_Wh;
            cp16(sb + soff[i], base + goff[i] + koff);
        }
        cp_commit();
    }

    // ---- main loop ----
    for (int c = 0; c < NCHUNK; ++c) {
        cp_wait2();
        __syncthreads();

        // issue chunk c+3 into stage (c+3)%4
        if (c + STAGES - 1 < NCHUNK) {
            const uint32_t sb = tiles + ((c + STAGES - 1) & (STAGES - 1)) * STAGE_BYTES;
            const int koff = (c + STAGES - 1) * BK;
            #pragma unroll
            for (int i = 0; i < UPT; ++i) {
                const __half* base = (i < 8) ? g_Xh : g_Wh;
                cp16(sb + soff[i], base + goff[i] + koff);
            }
        }
        cp_commit();

        // compute chunk c from stage c%4, k-steps register double-buffered
        const uint32_t st = tiles + (c & (STAGES - 1)) * STAGE_BYTES;
        const uint32_t abase = st + a_base_off;
        const uint32_t bbase = st + b_base_off;

        uint32_t a[2][4][4], rb[2][4][4];

        // prefetch kk=0 fragments
        {
            const uint32_t acol = a_ku ^ a_xor;
            const uint32_t bcol = b_ku ^ b_xor;
            #pragma unroll
            for (int mt = 0; mt < 4; ++mt)
                LDSM_X4(a[0][mt][0], a[0][mt][1], a[0][mt][2], a[0][mt][3],
                        abase + (uint32_t)(mt * 2048) + acol);
            #pragma unroll
            for (int ng = 0; ng < 4; ++ng)
                LDSM_X4(rb[0][ng][0], rb[0][ng][1], rb[0][ng][2], rb[0][ng][3],
                        bbase + (uint32_t)(ng * 2048) + bcol);
        }

        #pragma unroll
        for (int kk = 0; kk < 4; ++kk) {
            const int cur = kk & 1, nxt = cur ^ 1;
            if (kk < 3) {   // prefetch kk+1 fragments before this step's MMAs
                const uint32_t acol = ((uint32_t)((kk + 1) * 32) + a_ku) ^ a_xor;
                const uint32_t bcol = ((uint32_t)((kk + 1) * 32) + b_ku) ^ b_xor;
                #pragma unroll
                for (int mt = 0; mt < 4; ++mt)
                    LDSM_X4(a[nxt][mt][0], a[nxt][mt][1], a[nxt][mt][2], a[nxt][mt][3],
                            abase + (uint32_t)(mt * 2048) + acol);
                #pragma unroll
                for (int ng = 0; ng < 4; ++ng)
                    LDSM_X4(rb[nxt][ng][0], rb[nxt][ng][1], rb[nxt][ng][2], rb[nxt][ng][3],
                            bbase + (uint32_t)(ng * 2048) + bcol);
            }
            #pragma unroll
            for (int mt = 0; mt < 4; ++mt) {
                #pragma unroll
                for (int ng = 0; ng < 4; ++ng) {
                    // n-tile (ng*2+0): n rows [ng*16+0..7]  -> {rb[cur][ng][0], rb[cur][ng][2]}
                    MMA16816(acc[mt][ng * 2 + 0][0], acc[mt][ng * 2 + 0][1],
                             acc[mt][ng * 2 + 0][2], acc[mt][ng * 2 + 0][3],
                             a[cur][mt][0], a[cur][mt][1], a[cur][mt][2], a[cur][mt][3],
                             rb[cur][ng][0], rb[cur][ng][2]);
                    // n-tile (ng*2+1): n rows [ng*16+8..15] -> {rb[cur][ng][1], rb[cur][ng][3]}
                    MMA16816(acc[mt][ng * 2 + 1][0], acc[mt][ng * 2 + 1][1],
                             acc[mt][ng * 2 + 1][2], acc[mt][ng * 2 + 1][3],
                             a[cur][mt][0], a[cur][mt][1], a[cur][mt][2], a[cur][mt][3],
                             rb[cur][ng][1], rb[cur][ng][3]);
                }
            }
        }
    }

    // ---- epilogue: bias + store fp32 ----
    {
        const int r0 = m0 + wm * 64 + (lane >> 2);
        const int cbase = n0 + wn * 64 + (lane & 3) * 2;
        const float2* bp = reinterpret_cast<const float2*>(bias + cbase);
        float2 bv[8];
        #pragma unroll
        for (int nt = 0; nt < 8; ++nt) bv[nt] = bp[nt * 4];   // +8 floats per n-tile

        #pragma unroll
        for (int mt = 0; mt < 4; ++mt) {
            const size_t rowa = (size_t)(r0 + mt * 16) * N_DIM;
            const size_t rowb = rowa + 8 * N_DIM;
            #pragma unroll
            for (int nt = 0; nt < 8; ++nt) {
                const int col = cbase + nt * 8;
                float2 o0, o1;
                o0.x = acc[mt][nt][0] + bv[nt].x;
                o0.y = acc[mt][nt][1] + bv[nt].y;
                o1.x = acc[mt][nt][2] + bv[nt].x;
                o1.y = acc[mt][nt][3] + bv[nt].y;
                *reinterpret_cast<float2*>(out + rowa + col) = o0;
                *reinterpret_cast<float2*>(out + rowb + col) = o1;
            }
        }
    }
}

// ---------------- launch ----------------
extern "C" void kernel_launch(void* const* d_in, const int* in_sizes, int n_in,
                              void* d_out, int out_size) {
    (void)in_sizes; (void)n_in; (void)out_size;
    const float* x = (const float*)d_in[0];
    const float* w = (const float*)d_in[1];
    const float* bias = (const float*)d_in[2];
    float* out = (float*)d_out;

    static int once = []() {
        cudaFuncSetAttribute(gemm_kernel, cudaFuncAttributeMaxDynamicSharedMemorySize, SMEM_DYN);
        return 0;
    }();
    (void)once;

    // 1) fused prep: weight fake-quant -> fp16 AND x -> fp16
    prep_kernel<<<QUANT_BLOCKS + CVT_BLOCKS, 256>>>((const float4*)w, (const float4*)x);
    // 2) fp16 mma.sync GEMM + bias
    dim3 grid(N_DIM / BN, M_DIM / BM);
    gemm_kernel<<<grid, THREADS, SMEM_DYN>>>(bias, out);
}